// round 4
// baseline (speedup 1.0000x reference)
#include <cuda_runtime.h>
#include <math.h>
#include <stdint.h>

#define NN 8192
#define F  256
#define ALPHA_C 0.2f

// ---------------- scratch ----------------
__device__ float    g_Wh[NN * F];     // fp32 Wh [i][n] (scores + source of pack)
__device__ uint32_t g_WhB[F * NN];    // tf32 Wh packed [chunk=j>>5][n][pk(j&31)]
__device__ float    g_ssrc[NN];
__device__ float    g_sdst[NN];
__device__ float    g_E0[NN];
__device__ float    g_E1[NN];
__device__ float    g_c0[NN];
__device__ float    g_c1[NN];
__device__ float    g_gmax;

// ---------------- helpers ----------------
__device__ __forceinline__ uint32_t f2tf(float x) {
    uint32_t r;
    asm("cvt.rna.tf32.f32 %0, %1;" : "=r"(r) : "f"(x));
    return r;
}
__device__ __forceinline__ void mma_tf32(float* d, const uint32_t* a, const uint32_t* b) {
    asm volatile(
        "mma.sync.aligned.m16n8k8.row.col.f32.tf32.tf32.f32 "
        "{%0,%1,%2,%3}, {%4,%5,%6,%7}, {%8,%9}, {%0,%1,%2,%3};\n"
        : "+f"(d[0]), "+f"(d[1]), "+f"(d[2]), "+f"(d[3])
        : "r"(a[0]), "r"(a[1]), "r"(a[2]), "r"(a[3]), "r"(b[0]), "r"(b[1]));
}

// ---------------- K1: Wh = X @ W^T (fp32) ----------------
__global__ void __launch_bounds__(256) k1_wh(const float* __restrict__ X,
                                             const float* __restrict__ W) {
    __shared__ float Xs[16][64];
    __shared__ float Ws[16][256];
    const int tid = threadIdx.x;
    const int i0  = blockIdx.x * 64;
    const int ty  = tid >> 5, tx = tid & 31;
    const int r   = tid & 63, kg = tid >> 6;

    float acc[8][8];
#pragma unroll
    for (int m = 0; m < 8; m++)
#pragma unroll
        for (int n = 0; n < 8; n++) acc[m][n] = 0.f;

    for (int f0 = 0; f0 < F; f0 += 16) {
        float4 xv = *(const float4*)&X[(i0 + r) * F + f0 + kg * 4];
        Xs[kg * 4 + 0][r] = xv.x;
        Xs[kg * 4 + 1][r] = xv.y;
        Xs[kg * 4 + 2][r] = xv.z;
        Xs[kg * 4 + 3][r] = xv.w;
        const float* wp = &W[tid * F + f0];
        float4 w0 = *(const float4*)(wp + 0);
        float4 w1 = *(const float4*)(wp + 4);
        float4 w2 = *(const float4*)(wp + 8);
        float4 w3 = *(const float4*)(wp + 12);
        Ws[0][tid]  = w0.x;  Ws[1][tid]  = w0.y;  Ws[2][tid]  = w0.z;  Ws[3][tid]  = w0.w;
        Ws[4][tid]  = w1.x;  Ws[5][tid]  = w1.y;  Ws[6][tid]  = w1.z;  Ws[7][tid]  = w1.w;
        Ws[8][tid]  = w2.x;  Ws[9][tid]  = w2.y;  Ws[10][tid] = w2.z;  Ws[11][tid] = w2.w;
        Ws[12][tid] = w3.x;  Ws[13][tid] = w3.y;  Ws[14][tid] = w3.z;  Ws[15][tid] = w3.w;
        __syncthreads();
#pragma unroll
        for (int kk = 0; kk < 16; kk++) {
            float av[8], bv[8];
            *(float4*)(av + 0) = *(const float4*)&Xs[kk][ty * 8 + 0];
            *(float4*)(av + 4) = *(const float4*)&Xs[kk][ty * 8 + 4];
            *(float4*)(bv + 0) = *(const float4*)&Ws[kk][tx * 4];
            *(float4*)(bv + 4) = *(const float4*)&Ws[kk][128 + tx * 4];
#pragma unroll
            for (int m = 0; m < 8; m++)
#pragma unroll
                for (int n = 0; n < 8; n++) acc[m][n] += av[m] * bv[n];
        }
        __syncthreads();
    }
#pragma unroll
    for (int m = 0; m < 8; m++) {
        int row = i0 + ty * 8 + m;
        *(float4*)&g_Wh[row * F + tx * 4]       = make_float4(acc[m][0], acc[m][1], acc[m][2], acc[m][3]);
        *(float4*)&g_Wh[row * F + 128 + tx * 4] = make_float4(acc[m][4], acc[m][5], acc[m][6], acc[m][7]);
    }
}

// ---------------- K1b: pack Wh -> g_WhB[chunk][n][pk] (tf32, k-permuted) ----------------
// pk(k): ks=k>>3, t=k&3, h=(k>>2)&1 -> pos = ks*8 + t*2 + h   (b0/b1 adjacent)
__global__ void __launch_bounds__(256) k1b_pack() {
    __shared__ float sm[32][33];
    const int j0 = blockIdx.x * 32;
    const int n0 = blockIdx.y * 32;
    const int x = threadIdx.x, y = threadIdx.y;    // 32 x 8
#pragma unroll
    for (int q = 0; q < 4; q++)
        sm[y + q * 8][x] = g_Wh[(size_t)(j0 + y + q * 8) * F + n0 + x];
    __syncthreads();
    // inverse perm: pos x -> k
    const int k = (x >> 3) * 8 + (x & 1) * 4 + ((x >> 1) & 3);
#pragma unroll
    for (int q = 0; q < 4; q++) {
        int nl = y + q * 8;
        g_WhB[(size_t)(j0 >> 5) * 8192 + (size_t)(n0 + nl) * 32 + x] = f2tf(sm[k][nl]);
    }
}

// ---------------- K2: scores ----------------
__global__ void __launch_bounds__(256) k2_scores(const float* __restrict__ r) {
    const int gwarp = (blockIdx.x * blockDim.x + threadIdx.x) >> 5;
    const int lane  = threadIdx.x & 31;
    if (gwarp >= NN) return;
    const float* row = &g_Wh[gwarp * F];
    float ss = 0.f, sd = 0.f;
#pragma unroll
    for (int q = 0; q < 8; q++) {
        int k = lane + q * 32;
        float v = row[k];
        ss += v * __ldg(&r[k]);
        sd += v * __ldg(&r[F + k]);
    }
#pragma unroll
    for (int o = 16; o > 0; o >>= 1) {
        ss += __shfl_xor_sync(0xffffffffu, ss, o);
        sd += __shfl_xor_sync(0xffffffffu, sd, o);
    }
    if (lane == 0) {
        g_ssrc[gwarp] = ss;
        g_sdst[gwarp] = sd;
    }
}

// ---------------- K3a: global max of sdst ----------------
__global__ void __launch_bounds__(1024) k3a_gmax() {
    __shared__ float red[1024];
    const int t = threadIdx.x;
    float m = -INFINITY;
    for (int q = t; q < NN; q += 1024) m = fmaxf(m, g_sdst[q]);
    red[t] = m;
    __syncthreads();
    for (int s = 512; s > 0; s >>= 1) {
        if (t < s) red[t] = fmaxf(red[t], red[t + s]);
        __syncthreads();
    }
    if (t == 0) g_gmax = red[0];
}

// ---------------- K3b: stable exp tables ----------------
__global__ void __launch_bounds__(256) k3b_tables() {
    const int i = blockIdx.x * blockDim.x + threadIdx.x;
    if (i >= NN) return;
    const float M  = g_gmax;
    const float sd = g_sdst[i];
    const float si = g_ssrc[i];
    g_E0[i] = expf(sd - M);
    g_E1[i] = expf(ALPHA_C * (sd - M));
    float u  = si + M;
    float mi = (u >= 0.f) ? u : ALPHA_C * u;
    g_c0[i] = expf(u - mi);
    g_c1[i] = expf(ALPHA_C * u - mi);
}

// ---------------- K4: tf32 mma, fragment-linear layouts, BM=64 x BN=128 ----------------
// smem: B bufs 2 x 18432 (128 rows x 144B), fragA 2 x 8192, zsh 1024, zinv 256
#define BBUF     18432
#define FRAG_OFF 36864
#define FRAGBUF  8192
#define ZSH_OFF  53248
#define ZINV_OFF 54272
#define K4_SMEM  54528

__global__ void __launch_bounds__(256, 2) k4_mma(const int* __restrict__ A,
                                                 float* __restrict__ out) {
    extern __shared__ char smem[];
    const int tid  = threadIdx.x, lane = tid & 31, warp = tid >> 5;
    const int i0    = blockIdx.x * 64;
    const int nbase = blockIdx.y * 128;
    const int g = lane >> 2, t = lane & 3;
    const int wy = warp >> 2, wx = warp & 3;

    // builder mapping: row r, 8 j per chunk (k-group kg)
    const int r  = tid & 63;
    const int kg = tid >> 6;
    const float c0 = g_c0[i0 + r];
    const float c1 = g_c1[i0 + r];
    const int4* arow = (const int4*)(A + (size_t)(i0 + r) * NN) + kg * 2;
    // fragA slot base for this (row, kg): quad ((blk*4+ks)*32 + g*4 + t), element half + 2h
    char* fbase_p = smem + FRAG_OFF +
                    ((((r >> 4) * 4 + kg) * 32 + (r & 7) * 4) * 16 + ((r >> 3) & 1) * 4);
    float zp = 0.f;

    // B loader mapping: row n = tid>>1, half-row (64B) = tid&1
    const uint32_t* bsrc0 = g_WhB + (size_t)(nbase + (tid >> 1)) * 32 + (tid & 1) * 16;
    uint32_t bdst0 = (uint32_t)__cvta_generic_to_shared(smem) + (tid >> 1) * 144 + (tid & 1) * 64;

    float acc[2][4][4];
#pragma unroll
    for (int m = 0; m < 2; m++)
#pragma unroll
        for (int u = 0; u < 4; u++)
#pragma unroll
            for (int q = 0; q < 4; q++) acc[m][u][q] = 0.f;

    // prologue: A regs chunk0 + B chunk0
    int4 cA0 = __ldg(arow + 0);
    int4 cA1 = __ldg(arow + 1);
    {
        const uint32_t* src = bsrc0;
#pragma unroll
        for (int q = 0; q < 4; q++)
            asm volatile("cp.async.cg.shared.global [%0], [%1], 16;"
                         :: "r"(bdst0 + q * 16), "l"(src + q * 4));
        asm volatile("cp.async.commit_group;");
    }

    for (int it = 0; it < NN / 32; ++it) {
        const int s = it & 1;

        // prefetch next A-mask into regs
        int4 nA0, nA1;
        if (it < NN / 32 - 1) {
            nA0 = __ldg(arow + (it + 1) * 8);
            nA1 = __ldg(arow + (it + 1) * 8 + 1);
        }

        // build w fragment quads for this chunk
        {
            const int jb = it * 32 + kg * 8;
            float4 e0a = *(const float4*)(g_E0 + jb);
            float4 e0b = *(const float4*)(g_E0 + jb + 4);
            float4 e1a = *(const float4*)(g_E1 + jb);
            float4 e1b = *(const float4*)(g_E1 + jb + 4);
            char* fb = fbase_p + s * FRAGBUF;
            uint32_t w0 = f2tf(fmaxf(c0 * e0a.x, c1 * e1a.x)) & (uint32_t)(-cA0.x);
            uint32_t w1 = f2tf(fmaxf(c0 * e0a.y, c1 * e1a.y)) & (uint32_t)(-cA0.y);
            uint32_t w2 = f2tf(fmaxf(c0 * e0a.z, c1 * e1a.z)) & (uint32_t)(-cA0.z);
            uint32_t w3 = f2tf(fmaxf(c0 * e0a.w, c1 * e1a.w)) & (uint32_t)(-cA0.w);
            uint32_t w4 = f2tf(fmaxf(c0 * e0b.x, c1 * e1b.x)) & (uint32_t)(-cA1.x);
            uint32_t w5 = f2tf(fmaxf(c0 * e0b.y, c1 * e1b.y)) & (uint32_t)(-cA1.y);
            uint32_t w6 = f2tf(fmaxf(c0 * e0b.z, c1 * e1b.z)) & (uint32_t)(-cA1.z);
            uint32_t w7 = f2tf(fmaxf(c0 * e0b.w, c1 * e1b.w)) & (uint32_t)(-cA1.w);
            *(uint32_t*)(fb + 0 * 16 + 0) = w0;
            *(uint32_t*)(fb + 1 * 16 + 0) = w1;
            *(uint32_t*)(fb + 2 * 16 + 0) = w2;
            *(uint32_t*)(fb + 3 * 16 + 0) = w3;
            *(uint32_t*)(fb + 0 * 16 + 8) = w4;
            *(uint32_t*)(fb + 1 * 16 + 8) = w5;
            *(uint32_t*)(fb + 2 * 16 + 8) = w6;
            *(uint32_t*)(fb + 3 * 16 + 8) = w7;
            zp += (__uint_as_float(w0) + __uint_as_float(w1)) +
                  (__uint_as_float(w2) + __uint_as_float(w3)) +
                  (__uint_as_float(w4) + __uint_as_float(w5)) +
                  (__uint_as_float(w6) + __uint_as_float(w7));
        }

        asm volatile("cp.async.wait_group 0;");
        __syncthreads();

        // issue next B tile into the other buffer
        if (it < NN / 32 - 1) {
            const uint32_t* src = bsrc0 + (size_t)(it + 1) * 8192;
            uint32_t dst = bdst0 + (s ^ 1) * BBUF;
#pragma unroll
            for (int q = 0; q < 4; q++)
                asm volatile("cp.async.cg.shared.global [%0], [%1], 16;"
                             :: "r"(dst + q * 16), "l"(src + q * 4));
            asm volatile("cp.async.commit_group;");
        }

        // mma over this chunk
        {
            const char* bb = smem + s * BBUF;
            const char* fa = smem + FRAG_OFF + s * FRAGBUF;
#pragma unroll
            for (int ks = 0; ks < 4; ks++) {
                uint4 afq[2];
                afq[0] = *(const uint4*)(fa + (((wy * 2 + 0) * 4 + ks) * 32 + lane) * 16);
                afq[1] = *(const uint4*)(fa + (((wy * 2 + 1) * 4 + ks) * 32 + lane) * 16);
                uint2 bfq[4];
#pragma unroll
                for (int u = 0; u < 4; u++)
                    bfq[u] = *(const uint2*)(bb + (wx * 32 + u * 8 + g) * 144 + ks * 32 + t * 8);
#pragma unroll
                for (int m = 0; m < 2; m++)
#pragma unroll
                    for (int u = 0; u < 4; u++)
                        mma_tf32(acc[m][u], (const uint32_t*)&afq[m], (const uint32_t*)&bfq[u]);
            }
        }

        cA0 = nA0;
        cA1 = nA1;
    }

    // ---- Z reduce (deterministic) ----
    float* zsh  = (float*)(smem + ZSH_OFF);
    float* zinv = (float*)(smem + ZINV_OFF);
    __syncthreads();
    zsh[tid] = zp;
    __syncthreads();
    if (tid < 64)
        zinv[tid] = 1.0f / ((zsh[tid] + zsh[tid + 64]) + (zsh[tid + 128] + zsh[tid + 192]));
    __syncthreads();

    // ---- epilogue: /Z, exact GELU, store ----
#pragma unroll
    for (int m = 0; m < 2; m++) {
        int rr = wy * 32 + m * 16 + g;
        float zi0 = zinv[rr];
        float zi1 = zinv[rr + 8];
#pragma unroll
        for (int u = 0; u < 4; u++) {
            int col = nbase + wx * 32 + u * 8 + t * 2;
            float x0 = acc[m][u][0] * zi0;
            float x1 = acc[m][u][1] * zi0;
            float x2 = acc[m][u][2] * zi1;
            float x3 = acc[m][u][3] * zi1;
            float g0 = 0.5f * x0 * (1.0f + erff(x0 * 0.70710678118654752f));
            float g1 = 0.5f * x1 * (1.0f + erff(x1 * 0.70710678118654752f));
            float g2 = 0.5f * x2 * (1.0f + erff(x2 * 0.70710678118654752f));
            float g3 = 0.5f * x3 * (1.0f + erff(x3 * 0.70710678118654752f));
            *(float2*)&out[(size_t)(i0 + rr) * F + col]     = make_float2(g0, g1);
            *(float2*)&out[(size_t)(i0 + rr + 8) * F + col] = make_float2(g2, g3);
        }
    }
}

// ---------------- launch ----------------
extern "C" void kernel_launch(void* const* d_in, const int* in_sizes, int n_in,
                              void* d_out, int out_size) {
    (void)in_sizes; (void)n_in; (void)out_size;
    const float* X = (const float*)d_in[0];
    const int*   A = (const int*)d_in[1];
    const float* W = (const float*)d_in[2];
    const float* r = (const float*)d_in[3];
    float* out = (float*)d_out;

    cudaFuncSetAttribute(k4_mma, cudaFuncAttributeMaxDynamicSharedMemorySize, K4_SMEM);

    k1_wh<<<NN / 64, 256>>>(X, W);
    k1b_pack<<<dim3(NN / 32, F / 32), dim3(32, 8)>>>();
    k2_scores<<<(NN * 32) / 256, 256>>>(r);
    k3a_gmax<<<1, 1024>>>();
    k3b_tables<<<NN / 256, 256>>>();
    k4_mma<<<dim3(NN / 64, 2), 256, K4_SMEM>>>(A, out);
}

// round 5
// speedup vs baseline: 2.0769x; 2.0769x over previous
#include <cuda_runtime.h>
#include <cuda_fp16.h>
#include <math.h>
#include <stdint.h>

#define NN 8192
#define F  256
#define ALPHA_C 0.2f

// ---------------- scratch ----------------
__device__ float    g_Wh[NN * F];        // fp32 Wh [i][n]
__device__ uint32_t g_WhBh[NN / 32 * F * 16];  // fp16 Wh, B-fragment order: [chunk][n][pair]
__device__ float    g_ssrc[NN];
__device__ float    g_sdst[NN];
__device__ float    g_E0[NN];
__device__ float    g_E1[NN];
__device__ float    g_c0[NN];
__device__ float    g_c1[NN];
__device__ float    g_gmax;

// ---------------- helpers ----------------
__device__ __forceinline__ void mma_f16(float* d, const uint32_t* a, uint32_t b0, uint32_t b1) {
    asm volatile(
        "mma.sync.aligned.m16n8k16.row.col.f32.f16.f16.f32 "
        "{%0,%1,%2,%3}, {%4,%5,%6,%7}, {%8,%9}, {%0,%1,%2,%3};\n"
        : "+f"(d[0]), "+f"(d[1]), "+f"(d[2]), "+f"(d[3])
        : "r"(a[0]), "r"(a[1]), "r"(a[2]), "r"(a[3]), "r"(b0), "r"(b1));
}

// ---------------- K1: Wh = X @ W^T (fp32), BM=64 x BN=128 ----------------
__global__ void __launch_bounds__(256) k1_wh(const float* __restrict__ X,
                                             const float* __restrict__ W) {
    __shared__ float Xs[16][64];
    __shared__ float Ws[16][128];
    const int tid = threadIdx.x;
    const int i0  = blockIdx.x * 64;
    const int nb  = blockIdx.y * 128;
    const int ty  = tid >> 5, tx = tid & 31;
    const int r   = tid & 63, kg = tid >> 6;
    const int o   = tid & 127, kh = tid >> 7;

    float acc[8][4];
#pragma unroll
    for (int m = 0; m < 8; m++)
#pragma unroll
        for (int n = 0; n < 4; n++) acc[m][n] = 0.f;

    for (int f0 = 0; f0 < F; f0 += 16) {
        float4 xv = *(const float4*)&X[(size_t)(i0 + r) * F + f0 + kg * 4];
        Xs[kg * 4 + 0][r] = xv.x;
        Xs[kg * 4 + 1][r] = xv.y;
        Xs[kg * 4 + 2][r] = xv.z;
        Xs[kg * 4 + 3][r] = xv.w;
        const float* wp = &W[(size_t)(nb + o) * F + f0 + kh * 8];
        float4 w0 = *(const float4*)(wp + 0);
        float4 w1 = *(const float4*)(wp + 4);
        Ws[kh * 8 + 0][o] = w0.x;  Ws[kh * 8 + 1][o] = w0.y;
        Ws[kh * 8 + 2][o] = w0.z;  Ws[kh * 8 + 3][o] = w0.w;
        Ws[kh * 8 + 4][o] = w1.x;  Ws[kh * 8 + 5][o] = w1.y;
        Ws[kh * 8 + 6][o] = w1.z;  Ws[kh * 8 + 7][o] = w1.w;
        __syncthreads();
#pragma unroll
        for (int kk = 0; kk < 16; kk++) {
            float av[8], bv[4];
            *(float4*)(av + 0) = *(const float4*)&Xs[kk][ty * 8 + 0];
            *(float4*)(av + 4) = *(const float4*)&Xs[kk][ty * 8 + 4];
            *(float4*)(bv + 0) = *(const float4*)&Ws[kk][tx * 4];
#pragma unroll
            for (int m = 0; m < 8; m++)
#pragma unroll
                for (int n = 0; n < 4; n++) acc[m][n] += av[m] * bv[n];
        }
        __syncthreads();
    }
#pragma unroll
    for (int m = 0; m < 8; m++) {
        int row = i0 + ty * 8 + m;
        *(float4*)&g_Wh[(size_t)row * F + nb + tx * 4] =
            make_float4(acc[m][0], acc[m][1], acc[m][2], acc[m][3]);
    }
}

// ---------------- K1b: pack Wh -> fp16 B-fragment order ----------------
// per chunk (32 j) per row n: 16 u32 pairs; pair pi: t=pi>>2, ks=(pi>>1)&1, hi8=pi&1
// covers j = ks*16 + 2t + 8*hi8 (+1)
__global__ void __launch_bounds__(256) k1b_pack() {
    __shared__ float sm[32][33];
    const int j0 = blockIdx.x * 32;
    const int n0 = blockIdx.y * 32;
    const int x = threadIdx.x, y = threadIdx.y;   // 32 x 8
#pragma unroll
    for (int q = 0; q < 4; q++)
        sm[y + q * 8][x] = g_Wh[(size_t)(j0 + y + q * 8) * F + n0 + x];
    __syncthreads();
    const int pi  = x & 15;
    const int nbs = x >> 4;
    const int t   = pi >> 2, ks = (pi >> 1) & 1, hi8 = pi & 1;
    const int jl  = ks * 16 + 2 * t + 8 * hi8;
#pragma unroll
    for (int q = 0; q < 2; q++) {
        int nl = y + nbs * 8 + q * 16;
        __half2 h = __floats2half2_rn(sm[jl][nl], sm[jl + 1][nl]);
        g_WhBh[(size_t)(j0 >> 5) * (F * 16) + (size_t)(n0 + nl) * 16 + pi] =
            *(const uint32_t*)&h;
    }
}

// ---------------- K2: scores ----------------
__global__ void __launch_bounds__(256) k2_scores(const float* __restrict__ r) {
    const int gwarp = (blockIdx.x * blockDim.x + threadIdx.x) >> 5;
    const int lane  = threadIdx.x & 31;
    if (gwarp >= NN) return;
    const float* row = &g_Wh[(size_t)gwarp * F];
    float ss = 0.f, sd = 0.f;
#pragma unroll
    for (int q = 0; q < 8; q++) {
        int k = lane + q * 32;
        float v = row[k];
        ss += v * __ldg(&r[k]);
        sd += v * __ldg(&r[F + k]);
    }
#pragma unroll
    for (int o = 16; o > 0; o >>= 1) {
        ss += __shfl_xor_sync(0xffffffffu, ss, o);
        sd += __shfl_xor_sync(0xffffffffu, sd, o);
    }
    if (lane == 0) {
        g_ssrc[gwarp] = ss;
        g_sdst[gwarp] = sd;
    }
}

// ---------------- K3a: global max of sdst ----------------
__global__ void __launch_bounds__(1024) k3a_gmax() {
    __shared__ float red[1024];
    const int t = threadIdx.x;
    float m = -INFINITY;
    for (int q = t; q < NN; q += 1024) m = fmaxf(m, g_sdst[q]);
    red[t] = m;
    __syncthreads();
    for (int s = 512; s > 0; s >>= 1) {
        if (t < s) red[t] = fmaxf(red[t], red[t + s]);
        __syncthreads();
    }
    if (t == 0) g_gmax = red[0];
}

// ---------------- K3b: stable exp tables ----------------
__global__ void __launch_bounds__(256) k3b_tables() {
    const int i = blockIdx.x * blockDim.x + threadIdx.x;
    if (i >= NN) return;
    const float M  = g_gmax;
    const float sd = g_sdst[i];
    const float si = g_ssrc[i];
    g_E0[i] = expf(sd - M);
    g_E1[i] = expf(ALPHA_C * (sd - M));
    float u  = si + M;
    float mi = (u >= 0.f) ? u : ALPHA_C * u;
    g_c0[i] = expf(u - mi);
    g_c1[i] = expf(ALPHA_C * u - mi);
}

// ---------------- K4: fp16 mma, BM=64 x BN=256, 512 threads, grid=128 ----------------
// smem: B 2 x 16384 @0 ; fragA 2 x 4096 @32768 ; zsh 512f @40960 ; zinv 64f @43008
#define BBUF     16384
#define FRAG_OFF 32768
#define FRAGBUF  4096
#define ZSH_OFF  40960
#define ZINV_OFF 43008
#define K4_SMEM  43264

__global__ void __launch_bounds__(512) k4_mma(const int* __restrict__ A,
                                              float* __restrict__ out) {
    extern __shared__ char smem[];
    const int tid  = threadIdx.x, lane = tid & 31, warp = tid >> 5;
    const int i0 = blockIdx.x * 64;
    const int g = lane >> 2, t = lane & 3;
    const int my = warp >> 2, wx = warp & 3;

    // ---- builder mapping: row r, 4 j's at offset jo within each 32-chunk ----
    const int r  = tid >> 3;
    const int jo = (tid & 7) * 4;
    const float c0 = g_c0[i0 + r];
    const float c1 = g_c1[i0 + r];
    const int4* arow = (const int4*)(A + (size_t)(i0 + r) * NN) + (jo >> 2);
    // A-fragment slot: ((my_r*2+ks)*32 + g_r*4 + tA)*16 + hi*8 + h*4
    const int ks_b = jo >> 4, kk = jo & 15;
    const int tA = (kk & 7) >> 1, hi = kk >> 3;
    char* fb0 = smem + FRAG_OFF +
                ((((r >> 4) * 2 + ks_b) * 32 + (r & 7) * 4 + tA) * 16 + hi * 8 + ((r >> 3) & 1) * 4);
    float zp = 0.f;

    // ---- B loader mapping: row n = tid>>1, half = tid&1 (8 u32 = 32B each) ----
    const uint32_t* bsrc = g_WhBh + (size_t)(tid >> 1) * 16 + (size_t)(tid & 1) * 8;
    const uint32_t bdst = (uint32_t)__cvta_generic_to_shared(smem) + (tid >> 1) * 64 + (tid & 1) * 32;

    float acc[8][4];
#pragma unroll
    for (int u = 0; u < 8; u++)
#pragma unroll
        for (int q = 0; q < 4; q++) acc[u][q] = 0.f;

    // ---- prologue ----
    int4 cA = __ldg(arow);
    {
        asm volatile("cp.async.cg.shared.global [%0], [%1], 16;" :: "r"(bdst), "l"(bsrc));
        asm volatile("cp.async.cg.shared.global [%0], [%1], 16;" :: "r"(bdst + 16), "l"(bsrc + 4));
        asm volatile("cp.async.commit_group;");
    }

    for (int it = 0; it < NN / 32; ++it) {
        const int s = it & 1;

        int4 nA;
        if (it < NN / 32 - 1) nA = __ldg(arow + (it + 1) * 8);

        // ---- build 4 w values (fp32 -> fp16 pairs, masked) ----
        {
            const int j = it * 32 + jo;
            float4 e0 = *(const float4*)(g_E0 + j);
            float4 e1 = *(const float4*)(g_E1 + j);
            float w0 = fmaxf(c0 * e0.x, c1 * e1.x);
            float w1 = fmaxf(c0 * e0.y, c1 * e1.y);
            float w2 = fmaxf(c0 * e0.z, c1 * e1.z);
            float w3 = fmaxf(c0 * e0.w, c1 * e1.w);
            __half2 p0 = __floats2half2_rn(w0, w1);
            __half2 p1 = __floats2half2_rn(w2, w3);
            uint32_t m0 = (cA.x ? 0x0000FFFFu : 0u) | (cA.y ? 0xFFFF0000u : 0u);
            uint32_t m1 = (cA.z ? 0x0000FFFFu : 0u) | (cA.w ? 0xFFFF0000u : 0u);
            uint32_t b0 = (*(const uint32_t*)&p0) & m0;
            uint32_t b1 = (*(const uint32_t*)&p1) & m1;
            char* fb = fb0 + s * FRAGBUF;
            *(uint32_t*)(fb)      = b0;
            *(uint32_t*)(fb + 16) = b1;   // t+1 slot
            float2 z0 = __half22float2(*(const __half2*)&b0);
            float2 z1 = __half22float2(*(const __half2*)&b1);
            zp += (z0.x + z0.y) + (z1.x + z1.y);
        }

        asm volatile("cp.async.wait_group 0;");
        __syncthreads();

        // ---- issue next B tile ----
        if (it < NN / 32 - 1) {
            const uint32_t* src = bsrc + (size_t)(it + 1) * 4096;
            uint32_t dst = bdst + (s ^ 1) * BBUF;
            asm volatile("cp.async.cg.shared.global [%0], [%1], 16;" :: "r"(dst), "l"(src));
            asm volatile("cp.async.cg.shared.global [%0], [%1], 16;" :: "r"(dst + 16), "l"(src + 4));
            asm volatile("cp.async.commit_group;");
        }

        // ---- mma: 2 A-frag LDS.128 + 8 B LDS.128 + 16 HMMA ----
        {
            const char* bb = smem + s * BBUF;
            const char* fa = smem + FRAG_OFF + s * FRAGBUF;
            uint4 aq0 = *(const uint4*)(fa + ((my * 2 + 0) * 32 + lane) * 16);
            uint4 aq1 = *(const uint4*)(fa + ((my * 2 + 1) * 32 + lane) * 16);
#pragma unroll
            for (int u = 0; u < 8; u++) {
                uint4 bq = *(const uint4*)(bb + (wx * 64 + u * 8 + g) * 64 + t * 16);
                mma_f16(acc[u], (const uint32_t*)&aq0, bq.x, bq.y);
                mma_f16(acc[u], (const uint32_t*)&aq1, bq.z, bq.w);
            }
        }

        cA = nA;
    }

    // ---- Z reduce (deterministic) ----
    float* zsh  = (float*)(smem + ZSH_OFF);
    float* zinv = (float*)(smem + ZINV_OFF);
    __syncthreads();
    zsh[tid] = zp;
    __syncthreads();
    if (tid < 64) {
        const float* p = zsh + tid * 8;
        float z = ((p[0] + p[1]) + (p[2] + p[3])) + ((p[4] + p[5]) + (p[6] + p[7]));
        zinv[tid] = 1.0f / z;
    }
    __syncthreads();

    // ---- epilogue: /Z, exact GELU, store ----
    const int rr = my * 16 + g;
    const float zi0 = zinv[rr];
    const float zi1 = zinv[rr + 8];
#pragma unroll
    for (int u = 0; u < 8; u++) {
        int col = wx * 64 + u * 8 + t * 2;
        float x0 = acc[u][0] * zi0;
        float x1 = acc[u][1] * zi0;
        float x2 = acc[u][2] * zi1;
        float x3 = acc[u][3] * zi1;
        float g0 = 0.5f * x0 * (1.0f + erff(x0 * 0.70710678118654752f));
        float g1 = 0.5f * x1 * (1.0f + erff(x1 * 0.70710678118654752f));
        float g2 = 0.5f * x2 * (1.0f + erff(x2 * 0.70710678118654752f));
        float g3 = 0.5f * x3 * (1.0f + erff(x3 * 0.70710678118654752f));
        *(float2*)&out[(size_t)(i0 + rr) * F + col]     = make_float2(g0, g1);
        *(float2*)&out[(size_t)(i0 + rr + 8) * F + col] = make_float2(g2, g3);
    }
}

// ---------------- launch ----------------
extern "C" void kernel_launch(void* const* d_in, const int* in_sizes, int n_in,
                              void* d_out, int out_size) {
    (void)in_sizes; (void)n_in; (void)out_size;
    const float* X = (const float*)d_in[0];
    const int*   A = (const int*)d_in[1];
    const float* W = (const float*)d_in[2];
    const float* r = (const float*)d_in[3];
    float* out = (float*)d_out;

    cudaFuncSetAttribute(k4_mma, cudaFuncAttributeMaxDynamicSharedMemorySize, K4_SMEM);

    k1_wh<<<dim3(NN / 64, 2), 256>>>(X, W);
    k1b_pack<<<dim3(NN / 32, F / 32), dim3(32, 8)>>>();
    k2_scores<<<(NN * 32) / 256, 256>>>(r);
    k3a_gmax<<<1, 1024>>>();
    k3b_tables<<<NN / 256, 256>>>();
    k4_mma<<<NN / 64, 512, K4_SMEM>>>(A, out);
}